// round 15
// baseline (speedup 1.0000x reference)
#include <cuda_runtime.h>
#include <cuda_bf16.h>
#include <cuda_fp16.h>
#include <cstdint>

// ---------------------------------------------------------------------------
// SelfAttention B=8,S=2048,D=768. mma.sync tensor cores + mask row compaction.
//  R14 = R13 + batch-pipelined attention tail: scores/softmax/pv split into
//        per-batch launches alternated across two streams so the memory-bound
//        softmax overlaps tensor-bound GEMM work and wave tails backfill.
//  - Projections & scores: split-bf16 3-term (Ah·Bh + Ah·Bl + Al·Bh), fp32 acc
//  - attn@V: fp16 2-term (attn_h·Vh + attn_h·Vl), attn single fp16
//  - masked query rows -> NORM * mean_t V[b,t,:]
// ---------------------------------------------------------------------------

#define B_   8
#define S_   2048
#define D_   768
#define MTOT (B_ * S_)                     // 16384
#define NORM_CONST 0.036084391824351615f   // 1/sqrt(768)

// ------------------------------ scratch ------------------------------------
__device__ __align__(256) __nv_bfloat16 g_xh[MTOT * D_],  g_xl[MTOT * D_];
__device__ __align__(256) __nv_bfloat16 g_WqTh[D_ * D_],  g_WqTl[D_ * D_];
__device__ __align__(256) __nv_bfloat16 g_WkTh[D_ * D_],  g_WkTl[D_ * D_];
__device__ __align__(256) __nv_bfloat16 g_WvTh[D_ * D_],  g_WvTl[D_ * D_];
__device__ __align__(256) __nv_bfloat16 g_Qh[MTOT * D_],  g_Ql[MTOT * D_];   // compacted
__device__ __align__(256) __nv_bfloat16 g_Kh[MTOT * D_],  g_Kl[MTOT * D_];
__device__ __align__(256) __half        g_VTh[D_ * MTOT], g_VTl[D_ * MTOT];  // fp16
__device__ __align__(256) float         g_S[(size_t)B_ * S_ * S_];
__device__ __align__(256) __half        g_Att[(size_t)B_ * S_ * S_];         // fp16 attn
__device__ int   g_cnt[B_];
__device__ int   g_c2o[MTOT];         // compacted slot -> global orig row (-1 pad)
__device__ int   g_o2s[MTOT];         // orig row -> within-batch slot (-1 masked)
__device__ float g_mv[B_ * D_];

// --------------------------- PTX helpers -----------------------------------
__device__ __forceinline__ uint32_t smem_to_u32(const void* p) {
    uint32_t a;
    asm("{ .reg .u64 t; cvta.to.shared.u64 t, %1; cvt.u32.u64 %0, t; }"
        : "=r"(a) : "l"(p));
    return a;
}

__device__ __forceinline__ void ldsm4(uint32_t* r, uint32_t addr) {
    asm volatile("ldmatrix.sync.aligned.m8n8.x4.shared.b16 {%0,%1,%2,%3}, [%4];"
                 : "=r"(r[0]), "=r"(r[1]), "=r"(r[2]), "=r"(r[3]) : "r"(addr));
}

__device__ __forceinline__ void mma_bf16(float* c, const uint32_t* a,
                                         uint32_t b0, uint32_t b1) {
    asm volatile(
        "mma.sync.aligned.m16n8k16.row.col.f32.bf16.bf16.f32 "
        "{%0,%1,%2,%3}, {%4,%5,%6,%7}, {%8,%9}, {%0,%1,%2,%3};"
        : "+f"(c[0]), "+f"(c[1]), "+f"(c[2]), "+f"(c[3])
        : "r"(a[0]), "r"(a[1]), "r"(a[2]), "r"(a[3]), "r"(b0), "r"(b1));
}

__device__ __forceinline__ void mma_f16(float* c, const uint32_t* a,
                                        uint32_t b0, uint32_t b1) {
    asm volatile(
        "mma.sync.aligned.m16n8k16.row.col.f32.f16.f16.f32 "
        "{%0,%1,%2,%3}, {%4,%5,%6,%7}, {%8,%9}, {%0,%1,%2,%3};"
        : "+f"(c[0]), "+f"(c[1]), "+f"(c[2]), "+f"(c[3])
        : "r"(a[0]), "r"(a[1]), "r"(a[2]), "r"(a[3]), "r"(b0), "r"(b1));
}

// Swizzled offset for (row 0..127, 16B-chunk 0..3) in a 128x64B tile.
__device__ __forceinline__ uint32_t swzoff(int row, int chunk) {
    int line = row >> 1;
    int slot = (((row & 1) << 2) | chunk) ^ (line & 7);
    return (uint32_t)((line << 7) + (slot << 4));
}

#define CP16(dst, src) \
    asm volatile("cp.async.cg.shared.global [%0], [%1], 16;" \
                 :: "r"(dst), "l"(src) : "memory")
#define CP_COMMIT() asm volatile("cp.async.commit_group;" ::: "memory")
#define CP_WAIT1()  asm volatile("cp.async.wait_group 1;" ::: "memory")
#define CP_WAIT0()  asm volatile("cp.async.wait_group 0;" ::: "memory")

// ------------------------------ GEMM config --------------------------------
#define BKC 32
#define TILEB (128 * 64)                   // 8192 B
#define STAGEB (4 * TILEB)                 // 32 KB (Ah, Al, Bh, Bl)
#define NSTAGE 3
#define GEMM_SMEM (NSTAGE * STAGEB)        // 96 KB
#define STAGEB_PV (3 * TILEB)              // 24 KB (A, Bh, Bl)
#define PV_SMEM (NSTAGE * STAGEB_PV)       // 72 KB

__device__ __forceinline__ void copy_stage4(
    uint32_t st,
    const __nv_bfloat16* Ah, const __nv_bfloat16* Al, int lda,
    const __nv_bfloat16* Bh, const __nv_bfloat16* Bl, int ldb,
    int rowA0, int rowA1, int n0, int k0, int tid)
{
    const int rsel = tid >> 2;
    const int ch   = tid & 3;
    #pragma unroll
    for (int j = 0; j < 8; j++) {
        const int tile = j >> 1;
        const int half = j & 1;
        const int rowL = (half << 6) + rsel;
        const __nv_bfloat16* p = (tile == 0) ? Ah : (tile == 1) ? Al
                                : (tile == 2) ? Bh : Bl;
        const int ld   = (tile < 2) ? lda : ldb;
        const int rowG = (tile < 2) ? (half ? rowA1 : rowA0) : (n0 + rowL);
        const __nv_bfloat16* src = p + (long long)rowG * ld + k0 + ch * 8;
        CP16(st + tile * TILEB + swzoff(rowL, ch), src);
    }
}

// OUT_MODE: 0 fp32 direct (scores)
//           1 bf16split bias[col] (K proj)
//           2 fp16split bias[row] (V^T proj; Ch/Cl reinterpreted as __half*)
//           3 bf16split bias[col], A rows gathered via c2o, compacted out (Q proj)
template <int OUT_MODE>
__global__ __launch_bounds__(256, 2)
void mma_gemm_kernel(const __nv_bfloat16* __restrict__ Ah, const __nv_bfloat16* __restrict__ Al,
                     int lda, long long strideA,
                     const __nv_bfloat16* __restrict__ Bh, const __nv_bfloat16* __restrict__ Bl,
                     int ldb, long long strideB,
                     float* __restrict__ Cf,
                     __nv_bfloat16* __restrict__ Ch, __nv_bfloat16* __restrict__ Cl,
                     int ldc, long long strideC,
                     const float* __restrict__ bias, int Ktot,
                     const int* __restrict__ cntp, const int* __restrict__ rowmap)
{
    const long long bz = blockIdx.z;
    const int m0 = blockIdx.y * 128;
    if (cntp && m0 >= cntp[bz]) return;
    const int n0 = blockIdx.x * 128;

    extern __shared__ char smem[];
    const uint32_t sb = smem_to_u32(smem);
    const int tid  = threadIdx.x;
    const int wid  = tid >> 5;
    const int lane = tid & 31;
    const int wm   = wid & 3;
    const int wn   = wid >> 2;

    Ah += bz * strideA;  Al += bz * strideA;
    Bh += bz * strideB;  Bl += bz * strideB;

    const int rsel = tid >> 2;
    int rowA0, rowA1;
    if (OUT_MODE == 3) {
        const int* gm = rowmap + bz * S_;
        int g0 = gm[m0 + rsel];
        int g1 = gm[m0 + 64 + rsel];
        rowA0 = (g0 < 0) ? 0 : g0;
        rowA1 = (g1 < 0) ? 0 : g1;
    } else {
        rowA0 = m0 + rsel;
        rowA1 = rowA0 + 64;
    }

    float acc[2][8][4];
    #pragma unroll
    for (int i = 0; i < 2; i++)
        #pragma unroll
        for (int j = 0; j < 8; j++)
            #pragma unroll
            for (int q = 0; q < 4; q++) acc[i][j][q] = 0.f;

    const int lrow = lane & 15;
    const int NIT = Ktot / BKC;

    copy_stage4(sb, Ah, Al, lda, Bh, Bl, ldb, rowA0, rowA1, n0, 0, tid);
    CP_COMMIT();
    copy_stage4(sb + STAGEB, Ah, Al, lda, Bh, Bl, ldb, rowA0, rowA1, n0, BKC, tid);
    CP_COMMIT();

    int stage = 0;
    for (int it = 0; it < NIT; ++it) {
        if (it + 1 < NIT) CP_WAIT1(); else CP_WAIT0();
        __syncthreads();
        if (it + 2 < NIT) {
            int ns = stage + 2; if (ns >= NSTAGE) ns -= NSTAGE;
            copy_stage4(sb + ns * STAGEB, Ah, Al, lda, Bh, Bl, ldb,
                        rowA0, rowA1, n0, (it + 2) * BKC, tid);
            CP_COMMIT();
        }
        const uint32_t st = sb + stage * STAGEB;
        #pragma unroll
        for (int ks = 0; ks < 2; ks++) {
            const int ckc = ks * 2 + (lane >> 4);
            uint32_t afh[2][4], afl[2][4], bf[4][4];
            #pragma unroll
            for (int mf = 0; mf < 2; mf++) {
                uint32_t ra = st + swzoff(wm * 32 + mf * 16 + lrow, ckc);
                ldsm4(afh[mf], ra);
                ldsm4(afl[mf], ra + TILEB);
            }
            uint32_t rbb[4];
            #pragma unroll
            for (int g = 0; g < 4; g++) {
                rbb[g] = st + 2 * TILEB + swzoff(wn * 64 + g * 16 + lrow, ckc);
                ldsm4(bf[g], rbb[g]);                     // Bh
            }
            #pragma unroll
            for (int mf = 0; mf < 2; mf++)
                #pragma unroll
                for (int nf = 0; nf < 8; nf++) {
                    const int g = nf >> 1, h = nf & 1;
                    mma_bf16(acc[mf][nf], afh[mf], bf[g][h], bf[g][2 + h]);
                    mma_bf16(acc[mf][nf], afl[mf], bf[g][h], bf[g][2 + h]);
                }
            #pragma unroll
            for (int g = 0; g < 4; g++)
                ldsm4(bf[g], rbb[g] + TILEB);             // Bl
            #pragma unroll
            for (int mf = 0; mf < 2; mf++)
                #pragma unroll
                for (int nf = 0; nf < 8; nf++) {
                    const int g = nf >> 1, h = nf & 1;
                    mma_bf16(acc[mf][nf], afh[mf], bf[g][h], bf[g][2 + h]);
                }
        }
        stage = (stage + 1 == NSTAGE) ? 0 : stage + 1;
    }

    // ----------------------------- epilogue --------------------------------
    const int rbase = m0 + wm * 32 + (lane >> 2);
    const int cbase = n0 + wn * 64 + (lane & 3) * 2;
    #pragma unroll
    for (int mf = 0; mf < 2; mf++) {
        #pragma unroll
        for (int half = 0; half < 2; half++) {
            const int row = rbase + mf * 16 + half * 8;
            #pragma unroll
            for (int nf = 0; nf < 8; nf++) {
                const int col = cbase + nf * 8;
                float v0 = acc[mf][nf][half * 2 + 0];
                float v1 = acc[mf][nf][half * 2 + 1];
                if (OUT_MODE == 0) {
                    *(float2*)(Cf + bz * strideC + (long long)row * ldc + col)
                        = make_float2(v0, v1);
                } else if (OUT_MODE == 2) {
                    float rb2 = bias[row]; v0 += rb2; v1 += rb2;
                    __half h0 = __float2half_rn(v0);
                    __half h1 = __float2half_rn(v1);
                    __half l0 = __float2half_rn(v0 - __half2float(h0));
                    __half l1 = __float2half_rn(v1 - __half2float(h1));
                    __half2 hp; hp.x = h0; hp.y = h1;
                    __half2 lp; lp.x = l0; lp.y = l1;
                    *(__half2*)((__half*)Ch + (long long)row * ldc + col) = hp;
                    *(__half2*)((__half*)Cl + (long long)row * ldc + col) = lp;
                } else {
                    v0 += bias[col]; v1 += bias[col + 1];
                    __nv_bfloat16 h0 = __float2bfloat16_rn(v0);
                    __nv_bfloat16 h1 = __float2bfloat16_rn(v1);
                    __nv_bfloat16 l0 = __float2bfloat16_rn(v0 - __bfloat162float(h0));
                    __nv_bfloat16 l1 = __float2bfloat16_rn(v1 - __bfloat162float(h1));
                    __nv_bfloat162 hp; hp.x = h0; hp.y = h1;
                    __nv_bfloat162 lp; lp.x = l0; lp.y = l1;
                    *(__nv_bfloat162*)(Ch + bz * strideC + (long long)row * ldc + col) = hp;
                    *(__nv_bfloat162*)(Cl + bz * strideC + (long long)row * ldc + col) = lp;
                }
            }
        }
    }
}

// ------------------------------ PV kernel (fp16 2-term) ---------------------
__device__ __forceinline__ void copy_stage3(
    uint32_t st, const __half* A, int lda,
    const __half* Bh, const __half* Bl, int ldb,
    int m0, int n0, int k0, int tid)
{
    const int rsel = tid >> 2;
    const int ch   = tid & 3;
    #pragma unroll
    for (int j = 0; j < 6; j++) {
        const int tile = j >> 1;
        const int half = j & 1;
        const int rowL = (half << 6) + rsel;
        const __half* p = (tile == 0) ? A : (tile == 1) ? Bh : Bl;
        const int ld   = (tile == 0) ? lda : ldb;
        const int rowG = ((tile == 0) ? m0 : n0) + rowL;
        const __half* src = p + (long long)rowG * ld + k0 + ch * 8;
        CP16(st + tile * TILEB + swzoff(rowL, ch), src);
    }
}

// Per-batch pv: caller offsets attn/VT/c2o/cnt; grid z = 1.
__global__ __launch_bounds__(256, 2)
void pv_kernel(const __half* __restrict__ attn,
               const __half* __restrict__ VTh, const __half* __restrict__ VTl,
               float* __restrict__ out,
               const int* __restrict__ cnt, const int* __restrict__ c2o)
{
    const int m0 = blockIdx.y * 128;
    if (m0 >= cnt[0]) return;
    const int n0 = blockIdx.x * 128;

    extern __shared__ char smem[];
    const uint32_t sb = smem_to_u32(smem);
    const int tid  = threadIdx.x;
    const int wid  = tid >> 5;
    const int lane = tid & 31;
    const int wm   = wid & 3;
    const int wn   = wid >> 2;
    const int lrow = lane & 15;

    const __half* A  = attn;
    const __half* Bh = VTh;
    const __half* Bl = VTl;

    float acc[2][8][4];
    #pragma unroll
    for (int i = 0; i < 2; i++)
        #pragma unroll
        for (int j = 0; j < 8; j++)
            #pragma unroll
            for (int q = 0; q < 4; q++) acc[i][j][q] = 0.f;

    const int NIT = S_ / BKC;    // 64
    copy_stage3(sb, A, S_, Bh, Bl, MTOT, m0, n0, 0, tid);
    CP_COMMIT();
    copy_stage3(sb + STAGEB_PV, A, S_, Bh, Bl, MTOT, m0, n0, BKC, tid);
    CP_COMMIT();

    int stage = 0;
    for (int it = 0; it < NIT; ++it) {
        if (it + 1 < NIT) CP_WAIT1(); else CP_WAIT0();
        __syncthreads();
        if (it + 2 < NIT) {
            int ns = stage + 2; if (ns >= NSTAGE) ns -= NSTAGE;
            copy_stage3(sb + ns * STAGEB_PV, A, S_, Bh, Bl, MTOT,
                        m0, n0, (it + 2) * BKC, tid);
            CP_COMMIT();
        }
        const uint32_t st = sb + stage * STAGEB_PV;
        #pragma unroll
        for (int ks = 0; ks < 2; ks++) {
            const int ckc = ks * 2 + (lane >> 4);
            uint32_t af[2][4], bvh[4][4], bvl[4][4];
            #pragma unroll
            for (int mf = 0; mf < 2; mf++)
                ldsm4(af[mf], st + swzoff(wm * 32 + mf * 16 + lrow, ckc));
            #pragma unroll
            for (int g = 0; g < 4; g++) {
                uint32_t rb = st + TILEB + swzoff(wn * 64 + g * 16 + lrow, ckc);
                ldsm4(bvh[g], rb);
                ldsm4(bvl[g], rb + TILEB);
            }
            #pragma unroll
            for (int mf = 0; mf < 2; mf++)
                #pragma unroll
                for (int nf = 0; nf < 8; nf++) {
                    const int g = nf >> 1, h = nf & 1;
                    mma_f16(acc[mf][nf], af[mf], bvh[g][h], bvh[g][2 + h]);
                    mma_f16(acc[mf][nf], af[mf], bvl[g][h], bvl[g][2 + h]);
                }
        }
        stage = (stage + 1 == NSTAGE) ? 0 : stage + 1;
    }

    const int rbase = m0 + wm * 32 + (lane >> 2);
    const int cbase = n0 + wn * 64 + (lane & 3) * 2;
    #pragma unroll
    for (int mf = 0; mf < 2; mf++)
        #pragma unroll
        for (int half = 0; half < 2; half++) {
            const int row = rbase + mf * 16 + half * 8;
            const int drow = c2o[row];
            if (drow < 0) continue;
            #pragma unroll
            for (int nf = 0; nf < 8; nf++) {
                const int col = cbase + nf * 8;
                *(float2*)(out + (long long)drow * D_ + col)
                    = make_float2(acc[mf][nf][half * 2 + 0], acc[mf][nf][half * 2 + 1]);
            }
        }
}

// --------------------------- compaction ------------------------------------
__global__ __launch_bounds__(256)
void compact_kernel(const int* __restrict__ mask, int* __restrict__ cnt,
                    int* __restrict__ c2o, int* __restrict__ o2s)
{
    const int b = blockIdx.x, tid = threadIdx.x;
    const int lane = tid & 31, wid = tid >> 5;
    const int* m = mask + b * S_;
    __shared__ int wsum[8];
    __shared__ int s_tot;

    int loc[8], c = 0;
    #pragma unroll
    for (int i = 0; i < 8; i++) { loc[i] = (m[tid * 8 + i] != 0); c += loc[i]; }
    int pre = c;
    #pragma unroll
    for (int o = 1; o < 32; o <<= 1) {
        int v = __shfl_up_sync(0xffffffffu, pre, o);
        if (lane >= o) pre += v;
    }
    if (lane == 31) wsum[wid] = pre;
    __syncthreads();
    int wbase = 0;
    for (int w = 0; w < wid; w++) wbase += wsum[w];
    int slot = wbase + pre - c;
    #pragma unroll
    for (int i = 0; i < 8; i++) {
        int s = tid * 8 + i;
        if (loc[i]) { c2o[b * S_ + slot] = b * S_ + s; o2s[b * S_ + s] = slot; slot++; }
        else        { o2s[b * S_ + s] = -1; }
    }
    if (tid == 0) {
        int tot = 0;
        for (int w = 0; w < 8; w++) tot += wsum[w];
        cnt[b] = tot;
        s_tot = tot;
    }
    __syncthreads();
    for (int s = s_tot + tid; s < S_; s += 256) c2o[b * S_ + s] = -1;
}

// ------------------------- elementwise kernels -----------------------------
__global__ __launch_bounds__(256)
void split_kernel(const float* __restrict__ x, __nv_bfloat16* __restrict__ h,
                  __nv_bfloat16* __restrict__ l, int n)
{
    int i = (blockIdx.x * 256 + threadIdx.x) * 4;
    if (i + 3 < n) {
        float4 v = *(const float4*)(x + i);
        float vv[4] = {v.x, v.y, v.z, v.w};
        #pragma unroll
        for (int q = 0; q < 4; q++) {
            __nv_bfloat16 hh = __float2bfloat16_rn(vv[q]);
            h[i + q] = hh;
            l[i + q] = __float2bfloat16_rn(vv[q] - __bfloat162float(hh));
        }
    }
}

__global__ __launch_bounds__(256)
void transpose_split3_kernel(const float* __restrict__ Wq, const float* __restrict__ Wk,
                             const float* __restrict__ Wv,
                             __nv_bfloat16* __restrict__ qh, __nv_bfloat16* __restrict__ ql,
                             __nv_bfloat16* __restrict__ kh, __nv_bfloat16* __restrict__ kl,
                             __nv_bfloat16* __restrict__ vh, __nv_bfloat16* __restrict__ vl)
{
    int idx = blockIdx.x * 256 + threadIdx.x;
    if (idx >= D_ * D_) return;
    int j = idx / D_, i = idx - j * D_;
    const float* W = (blockIdx.y == 0) ? Wq : (blockIdx.y == 1) ? Wk : Wv;
    __nv_bfloat16* th = (blockIdx.y == 0) ? qh : (blockIdx.y == 1) ? kh : vh;
    __nv_bfloat16* tl = (blockIdx.y == 0) ? ql : (blockIdx.y == 1) ? kl : vl;
    float v = W[i * D_ + j];
    __nv_bfloat16 hh = __float2bfloat16_rn(v);
    th[idx] = hh;
    tl[idx] = __float2bfloat16_rn(v - __bfloat162float(hh));
}

__global__ __launch_bounds__(256)
void vmean_kernel(const __half* __restrict__ vth, const __half* __restrict__ vtl,
                  float* __restrict__ mv)
{
    const int d = blockIdx.x, b = blockIdx.y, tid = threadIdx.x;
    const __half* ph = vth + (long long)d * MTOT + b * S_;
    const __half* pl = vtl + (long long)d * MTOT + b * S_;
    float s = 0.f;
    #pragma unroll
    for (int i = 0; i < 8; i++) {
        int t = tid + i * 256;
        s += __half2float(ph[t]) + __half2float(pl[t]);
    }
    #pragma unroll
    for (int o = 16; o; o >>= 1) s += __shfl_xor_sync(0xffffffffu, s, o);
    __shared__ float ws[8];
    if ((tid & 31) == 0) ws[tid >> 5] = s;
    __syncthreads();
    if (tid == 0) {
        float t = 0.f;
        for (int w = 0; w < 8; w++) t += ws[w];
        mv[b * D_ + d] = t * (NORM_CONST / (float)S_);
    }
}

__global__ __launch_bounds__(256)
void fill_masked_kernel(const int* __restrict__ mask, const float* __restrict__ mv,
                        float* __restrict__ out)
{
    const int row = blockIdx.x;
    if (mask[row] != 0) return;
    const int b = row >> 11, tid = threadIdx.x;
    #pragma unroll
    for (int i = 0; i < 3; i++) {
        int d = tid + i * 256;
        out[(long long)row * D_ + d] = mv[b * D_ + d];
    }
}

// ------------------------------ softmax ------------------------------------
// Per-batch: caller offsets cnt/S/Att; grid = S_ blocks (row in [0,S_)).
__global__ __launch_bounds__(256)
void softmax_kernel(const int* __restrict__ cnt, const float* __restrict__ S,
                    __half* __restrict__ Att)
{
    const long long row = blockIdx.x;
    const int r = (int)row;
    const int c = cnt[0];
    const int cpad = (c + 127) & ~127;
    if (r >= cpad) return;
    const int tid = threadIdx.x;
    __half* ph = Att + row * S_;
    if (r >= c) {
        __half2 z; z.x = __float2half_rn(0.f); z.y = z.x;
        #pragma unroll
        for (int i = 0; i < 4; i++)
            ((__half2*)ph)[tid + i * 256] = z;
        return;
    }
    const float* p = S + row * S_;
    __shared__ float sred[8];

    float v[8];
    float mx = -3.0e38f;
    #pragma unroll
    for (int i = 0; i < 8; i++) { v[i] = p[tid + i * 256]; mx = fmaxf(mx, v[i]); }
    #pragma unroll
    for (int o = 16; o; o >>= 1) mx = fmaxf(mx, __shfl_xor_sync(0xffffffffu, mx, o));
    if ((tid & 31) == 0) sred[tid >> 5] = mx;
    __syncthreads();
    float rowmax = sred[0];
    #pragma unroll
    for (int w = 1; w < 8; w++) rowmax = fmaxf(rowmax, sred[w]);
    __syncthreads();

    float s = 0.f;
    #pragma unroll
    for (int i = 0; i < 8; i++) { v[i] = __expf(v[i] - rowmax); s += v[i]; }
    #pragma unroll
    for (int o = 16; o; o >>= 1) s += __shfl_xor_sync(0xffffffffu, s, o);
    if ((tid & 31) == 0) sred[tid >> 5] = s;
    __syncthreads();
    float rowsum = 0.f;
    #pragma unroll
    for (int w = 0; w < 8; w++) rowsum += sred[w];

    const float scale = NORM_CONST / rowsum;
    #pragma unroll
    for (int i = 0; i < 8; i++)
        ph[tid + i * 256] = __float2half_rn(v[i] * scale);
}

// ------------------------------- launch ------------------------------------
extern "C" void kernel_launch(void* const* d_in, const int* in_sizes, int n_in,
                              void* d_out, int out_size)
{
    const float* x    = (const float*)d_in[0];
    const int*   mask = (const int*)  d_in[1];
    const float* Wq   = (const float*)d_in[2];
    const float* bq   = (const float*)d_in[3];
    const float* Wk   = (const float*)d_in[4];
    const float* bk   = (const float*)d_in[5];
    const float* Wv   = (const float*)d_in[6];
    const float* bv   = (const float*)d_in[7];
    float* out = (float*)d_out;

    __nv_bfloat16 *xh, *xl, *WqTh, *WqTl, *WkTh, *WkTl, *WvTh, *WvTl;
    __nv_bfloat16 *Qh, *Ql, *Kh, *Kl;
    __half *VTh, *VTl, *Att;
    float *Sc, *mv;
    int *cnt, *c2o, *o2s;
    cudaGetSymbolAddress((void**)&xh, g_xh);     cudaGetSymbolAddress((void**)&xl, g_xl);
    cudaGetSymbolAddress((void**)&WqTh, g_WqTh); cudaGetSymbolAddress((void**)&WqTl, g_WqTl);
    cudaGetSymbolAddress((void**)&WkTh, g_WkTh); cudaGetSymbolAddress((void**)&WkTl, g_WkTl);
    cudaGetSymbolAddress((void**)&WvTh, g_WvTh); cudaGetSymbolAddress((void**)&WvTl, g_WvTl);
    cudaGetSymbolAddress((void**)&Qh, g_Qh);     cudaGetSymbolAddress((void**)&Ql, g_Ql);
    cudaGetSymbolAddress((void**)&Kh, g_Kh);     cudaGetSymbolAddress((void**)&Kl, g_Kl);
    cudaGetSymbolAddress((void**)&VTh, g_VTh);   cudaGetSymbolAddress((void**)&VTl, g_VTl);
    cudaGetSymbolAddress((void**)&Sc, g_S);
    cudaGetSymbolAddress((void**)&Att, g_Att);
    cudaGetSymbolAddress((void**)&cnt, g_cnt);
    cudaGetSymbolAddress((void**)&c2o, g_c2o);   cudaGetSymbolAddress((void**)&o2s, g_o2s);
    cudaGetSymbolAddress((void**)&mv, g_mv);

    cudaFuncSetAttribute(mma_gemm_kernel<0>, cudaFuncAttributeMaxDynamicSharedMemorySize, GEMM_SMEM);
    cudaFuncSetAttribute(mma_gemm_kernel<1>, cudaFuncAttributeMaxDynamicSharedMemorySize, GEMM_SMEM);
    cudaFuncSetAttribute(mma_gemm_kernel<2>, cudaFuncAttributeMaxDynamicSharedMemorySize, GEMM_SMEM);
    cudaFuncSetAttribute(mma_gemm_kernel<3>, cudaFuncAttributeMaxDynamicSharedMemorySize, GEMM_SMEM);
    cudaFuncSetAttribute(pv_kernel,          cudaFuncAttributeMaxDynamicSharedMemorySize, PV_SMEM);

    // Streams/events created ONCE on the first call (before the harness's
    // pre-capture memory baseline); reused by capture/replays.
    static cudaStream_t s1 = nullptr, s2 = nullptr;
    static cudaEvent_t eInit = nullptr, eK = nullptr, eQ = nullptr,
                       eVT = nullptr, eS2 = nullptr, eS1end = nullptr;
    if (s1 == nullptr) {
        cudaStreamCreateWithFlags(&s1, cudaStreamNonBlocking);
        cudaStreamCreateWithFlags(&s2, cudaStreamNonBlocking);
        cudaEventCreateWithFlags(&eInit,  cudaEventDisableTiming);
        cudaEventCreateWithFlags(&eK,     cudaEventDisableTiming);
        cudaEventCreateWithFlags(&eQ,     cudaEventDisableTiming);
        cudaEventCreateWithFlags(&eVT,    cudaEventDisableTiming);
        cudaEventCreateWithFlags(&eS2,    cudaEventDisableTiming);
        cudaEventCreateWithFlags(&eS1end, cudaEventDisableTiming);
    }

    dim3 blk(256);

    // ---- s0 (origin): prep ----
    compact_kernel<<<B_, blk>>>(mask, cnt, c2o, o2s);
    split_kernel<<<(MTOT * D_ / 4 + 255) / 256, blk>>>(x, xh, xl, MTOT * D_);
    {
        dim3 g((D_ * D_ + 255) / 256, 3);
        transpose_split3_kernel<<<g, blk>>>(Wq, Wk, Wv, WqTh, WqTl, WkTh, WkTl, WvTh, WvTl);
    }
    cudaEventRecord(eInit, 0);
    cudaStreamWaitEvent(s1, eInit, 0);
    cudaStreamWaitEvent(s2, eInit, 0);

    // ---- s0: Q proj (compacted gather) ----
    {
        dim3 grid(D_ / 128, S_ / 128, B_);
        mma_gemm_kernel<3><<<grid, blk, GEMM_SMEM>>>(
            xh, xl, D_, 0, WqTh, WqTl, D_, 0,
            nullptr, Qh, Ql, D_, (long long)S_ * D_, bq, D_, cnt, c2o);
        cudaEventRecord(eQ, 0);
    }
    // ---- s1: K proj (concurrent) ----
    {
        dim3 grid(D_ / 128, MTOT / 128, 1);
        mma_gemm_kernel<1><<<grid, blk, GEMM_SMEM, s1>>>(
            xh, xl, D_, 0, WkTh, WkTl, D_, 0,
            nullptr, Kh, Kl, D_, 0, bk, D_, nullptr, nullptr);
        cudaEventRecord(eK, s1);
    }
    // ---- s2: V^T proj + vmean + masked fill (overlaps scores pipeline) ----
    {
        dim3 grid(MTOT / 128, D_ / 128, 1);
        mma_gemm_kernel<2><<<grid, blk, GEMM_SMEM, s2>>>(
            WvTh, WvTl, D_, 0, xh, xl, D_, 0,
            nullptr, (__nv_bfloat16*)VTh, (__nv_bfloat16*)VTl, MTOT, 0, bv, D_,
            nullptr, nullptr);
        cudaEventRecord(eVT, s2);
        dim3 g(D_, B_);
        vmean_kernel<<<g, blk, 0, s2>>>(VTh, VTl, mv);
        fill_masked_kernel<<<MTOT, blk, 0, s2>>>(mask, mv, out);
        cudaEventRecord(eS2, s2);
    }

    // ---- batch-pipelined scores -> softmax -> pv across s0/s1 ----
    // s0 already ordered after Qproj; make it wait for Kproj too.
    cudaStreamWaitEvent(0, eK, 0);
    // s1 already ordered after Kproj; make it wait for Qproj and VT.
    cudaStreamWaitEvent(s1, eQ, 0);
    cudaStreamWaitEvent(s1, eVT, 0);
    cudaStreamWaitEvent(0, eVT, 0);   // pv on s0 also needs VT

    for (int b = 0; b < B_; b++) {
        cudaStream_t st = (b & 1) ? s1 : (cudaStream_t)0;
        const long long sOff = (long long)b * S_ * S_;
        // scores_b: [2048 x 2048] tile grid, batch slice via pointer offset
        {
            dim3 grid(S_ / 128, S_ / 128, 1);
            mma_gemm_kernel<0><<<grid, blk, GEMM_SMEM, st>>>(
                Qh + (long long)b * S_ * D_, Ql + (long long)b * S_ * D_, D_, 0,
                Kh + (long long)b * S_ * D_, Kl + (long long)b * S_ * D_, D_, 0,
                Sc + sOff, nullptr, nullptr, S_, 0, nullptr, D_, cnt + b, nullptr);
        }
        // softmax_b
        softmax_kernel<<<S_, blk, 0, st>>>(cnt + b, Sc + sOff, Att + sOff);
        // pv_b (VT dependency satisfied via the stream-level eVT waits above)
        {
            dim3 grid(D_ / 128, S_ / 128, 1);
            pv_kernel<<<grid, blk, PV_SMEM, st>>>(
                Att + sOff, VTh + (long long)b * S_, VTl + (long long)b * S_,
                out, cnt + b, c2o + (long long)b * S_);
        }
    }

    // ---- join s1 and s2 back into origin ----
    cudaEventRecord(eS1end, s1);
    cudaStreamWaitEvent(0, eS1end, 0);
    cudaStreamWaitEvent(0, eS2, 0);
}

// round 16
// speedup vs baseline: 1.2294x; 1.2294x over previous
#include <cuda_runtime.h>
#include <cuda_bf16.h>
#include <cuda_fp16.h>
#include <cstdint>

// ---------------------------------------------------------------------------
// SelfAttention B=8,S=2048,D=768. mma.sync tensor cores + mask row compaction.
//  R15 = R13 (877us) + two-way half-split attention tail:
//   chain A (s0): scores(b0-3) -> softmax -> [eVT] pv ; chain B (s1) same for
//   b4-7. eVT waits sit immediately before pv only (R14's bug: eVT at stream
//   head blocked scores). Kernels identical to R13.
//  - Projections & scores: split-bf16 3-term (Ah·Bh + Ah·Bl + Al·Bh), fp32 acc
//  - attn@V: fp16 2-term (attn_h·Vh + attn_h·Vl), attn single fp16
//  - masked query rows -> NORM * mean_t V[b,t,:]
// ---------------------------------------------------------------------------

#define B_   8
#define S_   2048
#define D_   768
#define MTOT (B_ * S_)                     // 16384
#define NORM_CONST 0.036084391824351615f   // 1/sqrt(768)

// ------------------------------ scratch ------------------------------------
__device__ __align__(256) __nv_bfloat16 g_xh[MTOT * D_],  g_xl[MTOT * D_];
__device__ __align__(256) __nv_bfloat16 g_WqTh[D_ * D_],  g_WqTl[D_ * D_];
__device__ __align__(256) __nv_bfloat16 g_WkTh[D_ * D_],  g_WkTl[D_ * D_];
__device__ __align__(256) __nv_bfloat16 g_WvTh[D_ * D_],  g_WvTl[D_ * D_];
__device__ __align__(256) __nv_bfloat16 g_Qh[MTOT * D_],  g_Ql[MTOT * D_];   // compacted
__device__ __align__(256) __nv_bfloat16 g_Kh[MTOT * D_],  g_Kl[MTOT * D_];
__device__ __align__(256) __half        g_VTh[D_ * MTOT], g_VTl[D_ * MTOT];  // fp16
__device__ __align__(256) float         g_S[(size_t)B_ * S_ * S_];
__device__ __align__(256) __half        g_Att[(size_t)B_ * S_ * S_];         // fp16 attn
__device__ int   g_cnt[B_];
__device__ int   g_c2o[MTOT];         // compacted slot -> global orig row (-1 pad)
__device__ int   g_o2s[MTOT];         // orig row -> within-batch slot (-1 masked)
__device__ float g_mv[B_ * D_];

// --------------------------- PTX helpers -----------------------------------
__device__ __forceinline__ uint32_t smem_to_u32(const void* p) {
    uint32_t a;
    asm("{ .reg .u64 t; cvta.to.shared.u64 t, %1; cvt.u32.u64 %0, t; }"
        : "=r"(a) : "l"(p));
    return a;
}

__device__ __forceinline__ void ldsm4(uint32_t* r, uint32_t addr) {
    asm volatile("ldmatrix.sync.aligned.m8n8.x4.shared.b16 {%0,%1,%2,%3}, [%4];"
                 : "=r"(r[0]), "=r"(r[1]), "=r"(r[2]), "=r"(r[3]) : "r"(addr));
}

__device__ __forceinline__ void mma_bf16(float* c, const uint32_t* a,
                                         uint32_t b0, uint32_t b1) {
    asm volatile(
        "mma.sync.aligned.m16n8k16.row.col.f32.bf16.bf16.f32 "
        "{%0,%1,%2,%3}, {%4,%5,%6,%7}, {%8,%9}, {%0,%1,%2,%3};"
        : "+f"(c[0]), "+f"(c[1]), "+f"(c[2]), "+f"(c[3])
        : "r"(a[0]), "r"(a[1]), "r"(a[2]), "r"(a[3]), "r"(b0), "r"(b1));
}

__device__ __forceinline__ void mma_f16(float* c, const uint32_t* a,
                                        uint32_t b0, uint32_t b1) {
    asm volatile(
        "mma.sync.aligned.m16n8k16.row.col.f32.f16.f16.f32 "
        "{%0,%1,%2,%3}, {%4,%5,%6,%7}, {%8,%9}, {%0,%1,%2,%3};"
        : "+f"(c[0]), "+f"(c[1]), "+f"(c[2]), "+f"(c[3])
        : "r"(a[0]), "r"(a[1]), "r"(a[2]), "r"(a[3]), "r"(b0), "r"(b1));
}

// Swizzled offset for (row 0..127, 16B-chunk 0..3) in a 128x64B tile.
__device__ __forceinline__ uint32_t swzoff(int row, int chunk) {
    int line = row >> 1;
    int slot = (((row & 1) << 2) | chunk) ^ (line & 7);
    return (uint32_t)((line << 7) + (slot << 4));
}

#define CP16(dst, src) \
    asm volatile("cp.async.cg.shared.global [%0], [%1], 16;" \
                 :: "r"(dst), "l"(src) : "memory")
#define CP_COMMIT() asm volatile("cp.async.commit_group;" ::: "memory")
#define CP_WAIT1()  asm volatile("cp.async.wait_group 1;" ::: "memory")
#define CP_WAIT0()  asm volatile("cp.async.wait_group 0;" ::: "memory")

// ------------------------------ GEMM config --------------------------------
#define BKC 32
#define TILEB (128 * 64)                   // 8192 B
#define STAGEB (4 * TILEB)                 // 32 KB (Ah, Al, Bh, Bl)
#define NSTAGE 3
#define GEMM_SMEM (NSTAGE * STAGEB)        // 96 KB
#define STAGEB_PV (3 * TILEB)              // 24 KB (A, Bh, Bl)
#define PV_SMEM (NSTAGE * STAGEB_PV)       // 72 KB

__device__ __forceinline__ void copy_stage4(
    uint32_t st,
    const __nv_bfloat16* Ah, const __nv_bfloat16* Al, int lda,
    const __nv_bfloat16* Bh, const __nv_bfloat16* Bl, int ldb,
    int rowA0, int rowA1, int n0, int k0, int tid)
{
    const int rsel = tid >> 2;
    const int ch   = tid & 3;
    #pragma unroll
    for (int j = 0; j < 8; j++) {
        const int tile = j >> 1;
        const int half = j & 1;
        const int rowL = (half << 6) + rsel;
        const __nv_bfloat16* p = (tile == 0) ? Ah : (tile == 1) ? Al
                                : (tile == 2) ? Bh : Bl;
        const int ld   = (tile < 2) ? lda : ldb;
        const int rowG = (tile < 2) ? (half ? rowA1 : rowA0) : (n0 + rowL);
        const __nv_bfloat16* src = p + (long long)rowG * ld + k0 + ch * 8;
        CP16(st + tile * TILEB + swzoff(rowL, ch), src);
    }
}

// OUT_MODE: 0 fp32 direct (scores)
//           1 bf16split bias[col] (K proj)
//           2 fp16split bias[row] (V^T proj; Ch/Cl reinterpreted as __half*)
//           3 bf16split bias[col], A rows gathered via c2o, compacted out (Q proj)
template <int OUT_MODE>
__global__ __launch_bounds__(256, 2)
void mma_gemm_kernel(const __nv_bfloat16* __restrict__ Ah, const __nv_bfloat16* __restrict__ Al,
                     int lda, long long strideA,
                     const __nv_bfloat16* __restrict__ Bh, const __nv_bfloat16* __restrict__ Bl,
                     int ldb, long long strideB,
                     float* __restrict__ Cf,
                     __nv_bfloat16* __restrict__ Ch, __nv_bfloat16* __restrict__ Cl,
                     int ldc, long long strideC,
                     const float* __restrict__ bias, int Ktot,
                     const int* __restrict__ cntp, const int* __restrict__ rowmap)
{
    const long long bz = blockIdx.z;
    const int m0 = blockIdx.y * 128;
    if (cntp && m0 >= cntp[bz]) return;
    const int n0 = blockIdx.x * 128;

    extern __shared__ char smem[];
    const uint32_t sb = smem_to_u32(smem);
    const int tid  = threadIdx.x;
    const int wid  = tid >> 5;
    const int lane = tid & 31;
    const int wm   = wid & 3;
    const int wn   = wid >> 2;

    Ah += bz * strideA;  Al += bz * strideA;
    Bh += bz * strideB;  Bl += bz * strideB;

    const int rsel = tid >> 2;
    int rowA0, rowA1;
    if (OUT_MODE == 3) {
        const int* gm = rowmap + bz * S_;
        int g0 = gm[m0 + rsel];
        int g1 = gm[m0 + 64 + rsel];
        rowA0 = (g0 < 0) ? 0 : g0;
        rowA1 = (g1 < 0) ? 0 : g1;
    } else {
        rowA0 = m0 + rsel;
        rowA1 = rowA0 + 64;
    }

    float acc[2][8][4];
    #pragma unroll
    for (int i = 0; i < 2; i++)
        #pragma unroll
        for (int j = 0; j < 8; j++)
            #pragma unroll
            for (int q = 0; q < 4; q++) acc[i][j][q] = 0.f;

    const int lrow = lane & 15;
    const int NIT = Ktot / BKC;

    copy_stage4(sb, Ah, Al, lda, Bh, Bl, ldb, rowA0, rowA1, n0, 0, tid);
    CP_COMMIT();
    copy_stage4(sb + STAGEB, Ah, Al, lda, Bh, Bl, ldb, rowA0, rowA1, n0, BKC, tid);
    CP_COMMIT();

    int stage = 0;
    for (int it = 0; it < NIT; ++it) {
        if (it + 1 < NIT) CP_WAIT1(); else CP_WAIT0();
        __syncthreads();
        if (it + 2 < NIT) {
            int ns = stage + 2; if (ns >= NSTAGE) ns -= NSTAGE;
            copy_stage4(sb + ns * STAGEB, Ah, Al, lda, Bh, Bl, ldb,
                        rowA0, rowA1, n0, (it + 2) * BKC, tid);
            CP_COMMIT();
        }
        const uint32_t st = sb + stage * STAGEB;
        #pragma unroll
        for (int ks = 0; ks < 2; ks++) {
            const int ckc = ks * 2 + (lane >> 4);
            uint32_t afh[2][4], afl[2][4], bf[4][4];
            #pragma unroll
            for (int mf = 0; mf < 2; mf++) {
                uint32_t ra = st + swzoff(wm * 32 + mf * 16 + lrow, ckc);
                ldsm4(afh[mf], ra);
                ldsm4(afl[mf], ra + TILEB);
            }
            uint32_t rbb[4];
            #pragma unroll
            for (int g = 0; g < 4; g++) {
                rbb[g] = st + 2 * TILEB + swzoff(wn * 64 + g * 16 + lrow, ckc);
                ldsm4(bf[g], rbb[g]);                     // Bh
            }
            #pragma unroll
            for (int mf = 0; mf < 2; mf++)
                #pragma unroll
                for (int nf = 0; nf < 8; nf++) {
                    const int g = nf >> 1, h = nf & 1;
                    mma_bf16(acc[mf][nf], afh[mf], bf[g][h], bf[g][2 + h]);
                    mma_bf16(acc[mf][nf], afl[mf], bf[g][h], bf[g][2 + h]);
                }
            #pragma unroll
            for (int g = 0; g < 4; g++)
                ldsm4(bf[g], rbb[g] + TILEB);             // Bl
            #pragma unroll
            for (int mf = 0; mf < 2; mf++)
                #pragma unroll
                for (int nf = 0; nf < 8; nf++) {
                    const int g = nf >> 1, h = nf & 1;
                    mma_bf16(acc[mf][nf], afh[mf], bf[g][h], bf[g][2 + h]);
                }
        }
        stage = (stage + 1 == NSTAGE) ? 0 : stage + 1;
    }

    // ----------------------------- epilogue --------------------------------
    const int rbase = m0 + wm * 32 + (lane >> 2);
    const int cbase = n0 + wn * 64 + (lane & 3) * 2;
    #pragma unroll
    for (int mf = 0; mf < 2; mf++) {
        #pragma unroll
        for (int half = 0; half < 2; half++) {
            const int row = rbase + mf * 16 + half * 8;
            #pragma unroll
            for (int nf = 0; nf < 8; nf++) {
                const int col = cbase + nf * 8;
                float v0 = acc[mf][nf][half * 2 + 0];
                float v1 = acc[mf][nf][half * 2 + 1];
                if (OUT_MODE == 0) {
                    *(float2*)(Cf + bz * strideC + (long long)row * ldc + col)
                        = make_float2(v0, v1);
                } else if (OUT_MODE == 2) {
                    float rb2 = bias[row]; v0 += rb2; v1 += rb2;
                    __half h0 = __float2half_rn(v0);
                    __half h1 = __float2half_rn(v1);
                    __half l0 = __float2half_rn(v0 - __half2float(h0));
                    __half l1 = __float2half_rn(v1 - __half2float(h1));
                    __half2 hp; hp.x = h0; hp.y = h1;
                    __half2 lp; lp.x = l0; lp.y = l1;
                    *(__half2*)((__half*)Ch + (long long)row * ldc + col) = hp;
                    *(__half2*)((__half*)Cl + (long long)row * ldc + col) = lp;
                } else {
                    v0 += bias[col]; v1 += bias[col + 1];
                    __nv_bfloat16 h0 = __float2bfloat16_rn(v0);
                    __nv_bfloat16 h1 = __float2bfloat16_rn(v1);
                    __nv_bfloat16 l0 = __float2bfloat16_rn(v0 - __bfloat162float(h0));
                    __nv_bfloat16 l1 = __float2bfloat16_rn(v1 - __bfloat162float(h1));
                    __nv_bfloat162 hp; hp.x = h0; hp.y = h1;
                    __nv_bfloat162 lp; lp.x = l0; lp.y = l1;
                    *(__nv_bfloat162*)(Ch + bz * strideC + (long long)row * ldc + col) = hp;
                    *(__nv_bfloat162*)(Cl + bz * strideC + (long long)row * ldc + col) = lp;
                }
            }
        }
    }
}

// ------------------------------ PV kernel (fp16 2-term) ---------------------
__device__ __forceinline__ void copy_stage3(
    uint32_t st, const __half* A, int lda,
    const __half* Bh, const __half* Bl, int ldb,
    int m0, int n0, int k0, int tid)
{
    const int rsel = tid >> 2;
    const int ch   = tid & 3;
    #pragma unroll
    for (int j = 0; j < 6; j++) {
        const int tile = j >> 1;
        const int half = j & 1;
        const int rowL = (half << 6) + rsel;
        const __half* p = (tile == 0) ? A : (tile == 1) ? Bh : Bl;
        const int ld   = (tile == 0) ? lda : ldb;
        const int rowG = ((tile == 0) ? m0 : n0) + rowL;
        const __half* src = p + (long long)rowG * ld + k0 + ch * 8;
        CP16(st + tile * TILEB + swzoff(rowL, ch), src);
    }
}

// Batched pv over grid z (batch slice via caller base pointers + per-z strides).
__global__ __launch_bounds__(256, 2)
void pv_kernel(const __half* __restrict__ attn,
               const __half* __restrict__ VTh, const __half* __restrict__ VTl,
               float* __restrict__ out,
               const int* __restrict__ cnt, const int* __restrict__ c2o)
{
    const long long bz = blockIdx.z;
    const int m0 = blockIdx.y * 128;
    if (m0 >= cnt[bz]) return;
    const int n0 = blockIdx.x * 128;

    extern __shared__ char smem[];
    const uint32_t sb = smem_to_u32(smem);
    const int tid  = threadIdx.x;
    const int wid  = tid >> 5;
    const int lane = tid & 31;
    const int wm   = wid & 3;
    const int wn   = wid >> 2;
    const int lrow = lane & 15;

    const __half* A  = attn + bz * (long long)S_ * S_;
    const __half* Bh = VTh + bz * S_;
    const __half* Bl = VTl + bz * S_;

    float acc[2][8][4];
    #pragma unroll
    for (int i = 0; i < 2; i++)
        #pragma unroll
        for (int j = 0; j < 8; j++)
            #pragma unroll
            for (int q = 0; q < 4; q++) acc[i][j][q] = 0.f;

    const int NIT = S_ / BKC;    // 64
    copy_stage3(sb, A, S_, Bh, Bl, MTOT, m0, n0, 0, tid);
    CP_COMMIT();
    copy_stage3(sb + STAGEB_PV, A, S_, Bh, Bl, MTOT, m0, n0, BKC, tid);
    CP_COMMIT();

    int stage = 0;
    for (int it = 0; it < NIT; ++it) {
        if (it + 1 < NIT) CP_WAIT1(); else CP_WAIT0();
        __syncthreads();
        if (it + 2 < NIT) {
            int ns = stage + 2; if (ns >= NSTAGE) ns -= NSTAGE;
            copy_stage3(sb + ns * STAGEB_PV, A, S_, Bh, Bl, MTOT,
                        m0, n0, (it + 2) * BKC, tid);
            CP_COMMIT();
        }
        const uint32_t st = sb + stage * STAGEB_PV;
        #pragma unroll
        for (int ks = 0; ks < 2; ks++) {
            const int ckc = ks * 2 + (lane >> 4);
            uint32_t af[2][4], bvh[4][4], bvl[4][4];
            #pragma unroll
            for (int mf = 0; mf < 2; mf++)
                ldsm4(af[mf], st + swzoff(wm * 32 + mf * 16 + lrow, ckc));
            #pragma unroll
            for (int g = 0; g < 4; g++) {
                uint32_t rb = st + TILEB + swzoff(wn * 64 + g * 16 + lrow, ckc);
                ldsm4(bvh[g], rb);
                ldsm4(bvl[g], rb + TILEB);
            }
            #pragma unroll
            for (int mf = 0; mf < 2; mf++)
                #pragma unroll
                for (int nf = 0; nf < 8; nf++) {
                    const int g = nf >> 1, h = nf & 1;
                    mma_f16(acc[mf][nf], af[mf], bvh[g][h], bvh[g][2 + h]);
                    mma_f16(acc[mf][nf], af[mf], bvl[g][h], bvl[g][2 + h]);
                }
        }
        stage = (stage + 1 == NSTAGE) ? 0 : stage + 1;
    }

    const int rbase = m0 + wm * 32 + (lane >> 2);
    const int cbase = n0 + wn * 64 + (lane & 3) * 2;
    #pragma unroll
    for (int mf = 0; mf < 2; mf++)
        #pragma unroll
        for (int half = 0; half < 2; half++) {
            const int row = rbase + mf * 16 + half * 8;
            const int drow = c2o[bz * S_ + row];
            if (drow < 0) continue;
            #pragma unroll
            for (int nf = 0; nf < 8; nf++) {
                const int col = cbase + nf * 8;
                *(float2*)(out + (long long)drow * D_ + col)
                    = make_float2(acc[mf][nf][half * 2 + 0], acc[mf][nf][half * 2 + 1]);
            }
        }
}

// --------------------------- compaction ------------------------------------
__global__ __launch_bounds__(256)
void compact_kernel(const int* __restrict__ mask, int* __restrict__ cnt,
                    int* __restrict__ c2o, int* __restrict__ o2s)
{
    const int b = blockIdx.x, tid = threadIdx.x;
    const int lane = tid & 31, wid = tid >> 5;
    const int* m = mask + b * S_;
    __shared__ int wsum[8];
    __shared__ int s_tot;

    int loc[8], c = 0;
    #pragma unroll
    for (int i = 0; i < 8; i++) { loc[i] = (m[tid * 8 + i] != 0); c += loc[i]; }
    int pre = c;
    #pragma unroll
    for (int o = 1; o < 32; o <<= 1) {
        int v = __shfl_up_sync(0xffffffffu, pre, o);
        if (lane >= o) pre += v;
    }
    if (lane == 31) wsum[wid] = pre;
    __syncthreads();
    int wbase = 0;
    for (int w = 0; w < wid; w++) wbase += wsum[w];
    int slot = wbase + pre - c;
    #pragma unroll
    for (int i = 0; i < 8; i++) {
        int s = tid * 8 + i;
        if (loc[i]) { c2o[b * S_ + slot] = b * S_ + s; o2s[b * S_ + s] = slot; slot++; }
        else        { o2s[b * S_ + s] = -1; }
    }
    if (tid == 0) {
        int tot = 0;
        for (int w = 0; w < 8; w++) tot += wsum[w];
        cnt[b] = tot;
        s_tot = tot;
    }
    __syncthreads();
    for (int s = s_tot + tid; s < S_; s += 256) c2o[b * S_ + s] = -1;
}

// ------------------------- elementwise kernels -----------------------------
__global__ __launch_bounds__(256)
void split_kernel(const float* __restrict__ x, __nv_bfloat16* __restrict__ h,
                  __nv_bfloat16* __restrict__ l, int n)
{
    int i = (blockIdx.x * 256 + threadIdx.x) * 4;
    if (i + 3 < n) {
        float4 v = *(const float4*)(x + i);
        float vv[4] = {v.x, v.y, v.z, v.w};
        #pragma unroll
        for (int q = 0; q < 4; q++) {
            __nv_bfloat16 hh = __float2bfloat16_rn(vv[q]);
            h[i + q] = hh;
            l[i + q] = __float2bfloat16_rn(vv[q] - __bfloat162float(hh));
        }
    }
}

__global__ __launch_bounds__(256)
void transpose_split3_kernel(const float* __restrict__ Wq, const float* __restrict__ Wk,
                             const float* __restrict__ Wv,
                             __nv_bfloat16* __restrict__ qh, __nv_bfloat16* __restrict__ ql,
                             __nv_bfloat16* __restrict__ kh, __nv_bfloat16* __restrict__ kl,
                             __nv_bfloat16* __restrict__ vh, __nv_bfloat16* __restrict__ vl)
{
    int idx = blockIdx.x * 256 + threadIdx.x;
    if (idx >= D_ * D_) return;
    int j = idx / D_, i = idx - j * D_;
    const float* W = (blockIdx.y == 0) ? Wq : (blockIdx.y == 1) ? Wk : Wv;
    __nv_bfloat16* th = (blockIdx.y == 0) ? qh : (blockIdx.y == 1) ? kh : vh;
    __nv_bfloat16* tl = (blockIdx.y == 0) ? ql : (blockIdx.y == 1) ? kl : vl;
    float v = W[i * D_ + j];
    __nv_bfloat16 hh = __float2bfloat16_rn(v);
    th[idx] = hh;
    tl[idx] = __float2bfloat16_rn(v - __bfloat162float(hh));
}

__global__ __launch_bounds__(256)
void vmean_kernel(const __half* __restrict__ vth, const __half* __restrict__ vtl,
                  float* __restrict__ mv)
{
    const int d = blockIdx.x, b = blockIdx.y, tid = threadIdx.x;
    const __half* ph = vth + (long long)d * MTOT + b * S_;
    const __half* pl = vtl + (long long)d * MTOT + b * S_;
    float s = 0.f;
    #pragma unroll
    for (int i = 0; i < 8; i++) {
        int t = tid + i * 256;
        s += __half2float(ph[t]) + __half2float(pl[t]);
    }
    #pragma unroll
    for (int o = 16; o; o >>= 1) s += __shfl_xor_sync(0xffffffffu, s, o);
    __shared__ float ws[8];
    if ((tid & 31) == 0) ws[tid >> 5] = s;
    __syncthreads();
    if (tid == 0) {
        float t = 0.f;
        for (int w = 0; w < 8; w++) t += ws[w];
        mv[b * D_ + d] = t * (NORM_CONST / (float)S_);
    }
}

__global__ __launch_bounds__(256)
void fill_masked_kernel(const int* __restrict__ mask, const float* __restrict__ mv,
                        float* __restrict__ out)
{
    const int row = blockIdx.x;
    if (mask[row] != 0) return;
    const int b = row >> 11, tid = threadIdx.x;
    #pragma unroll
    for (int i = 0; i < 3; i++) {
        int d = tid + i * 256;
        out[(long long)row * D_ + d] = mv[b * D_ + d];
    }
}

// ------------------------------ softmax ------------------------------------
// Half-batch slice: caller passes cnt+b0, Sc+off, Att+off; row = blockIdx.x,
// local b = row>>11 indexes cnt correctly for the slice.
__global__ __launch_bounds__(256)
void softmax_kernel(const int* __restrict__ cnt, const float* __restrict__ S,
                    __half* __restrict__ Att)
{
    const long long row = blockIdx.x;
    const int b = (int)(row >> 11), r = (int)(row & (S_ - 1));
    const int c = cnt[b];
    const int cpad = (c + 127) & ~127;
    if (r >= cpad) return;
    const int tid = threadIdx.x;
    __half* ph = Att + row * S_;
    if (r >= c) {
        __half2 z; z.x = __float2half_rn(0.f); z.y = z.x;
        #pragma unroll
        for (int i = 0; i < 4; i++)
            ((__half2*)ph)[tid + i * 256] = z;
        return;
    }
    const float* p = S + row * S_;
    __shared__ float sred[8];

    float v[8];
    float mx = -3.0e38f;
    #pragma unroll
    for (int i = 0; i < 8; i++) { v[i] = p[tid + i * 256]; mx = fmaxf(mx, v[i]); }
    #pragma unroll
    for (int o = 16; o; o >>= 1) mx = fmaxf(mx, __shfl_xor_sync(0xffffffffu, mx, o));
    if ((tid & 31) == 0) sred[tid >> 5] = mx;
    __syncthreads();
    float rowmax = sred[0];
    #pragma unroll
    for (int w = 1; w < 8; w++) rowmax = fmaxf(rowmax, sred[w]);
    __syncthreads();

    float s = 0.f;
    #pragma unroll
    for (int i = 0; i < 8; i++) { v[i] = __expf(v[i] - rowmax); s += v[i]; }
    #pragma unroll
    for (int o = 16; o; o >>= 1) s += __shfl_xor_sync(0xffffffffu, s, o);
    if ((tid & 31) == 0) sred[tid >> 5] = s;
    __syncthreads();
    float rowsum = 0.f;
    #pragma unroll
    for (int w = 0; w < 8; w++) rowsum += sred[w];

    const float scale = NORM_CONST / rowsum;
    #pragma unroll
    for (int i = 0; i < 8; i++)
        ph[tid + i * 256] = __float2half_rn(v[i] * scale);
}

// ------------------------------- launch ------------------------------------
extern "C" void kernel_launch(void* const* d_in, const int* in_sizes, int n_in,
                              void* d_out, int out_size)
{
    const float* x    = (const float*)d_in[0];
    const int*   mask = (const int*)  d_in[1];
    const float* Wq   = (const float*)d_in[2];
    const float* bq   = (const float*)d_in[3];
    const float* Wk   = (const float*)d_in[4];
    const float* bk   = (const float*)d_in[5];
    const float* Wv   = (const float*)d_in[6];
    const float* bv   = (const float*)d_in[7];
    float* out = (float*)d_out;

    __nv_bfloat16 *xh, *xl, *WqTh, *WqTl, *WkTh, *WkTl, *WvTh, *WvTl;
    __nv_bfloat16 *Qh, *Ql, *Kh, *Kl;
    __half *VTh, *VTl, *Att;
    float *Sc, *mv;
    int *cnt, *c2o, *o2s;
    cudaGetSymbolAddress((void**)&xh, g_xh);     cudaGetSymbolAddress((void**)&xl, g_xl);
    cudaGetSymbolAddress((void**)&WqTh, g_WqTh); cudaGetSymbolAddress((void**)&WqTl, g_WqTl);
    cudaGetSymbolAddress((void**)&WkTh, g_WkTh); cudaGetSymbolAddress((void**)&WkTl, g_WkTl);
    cudaGetSymbolAddress((void**)&WvTh, g_WvTh); cudaGetSymbolAddress((void**)&WvTl, g_WvTl);
    cudaGetSymbolAddress((void**)&Qh, g_Qh);     cudaGetSymbolAddress((void**)&Ql, g_Ql);
    cudaGetSymbolAddress((void**)&Kh, g_Kh);     cudaGetSymbolAddress((void**)&Kl, g_Kl);
    cudaGetSymbolAddress((void**)&VTh, g_VTh);   cudaGetSymbolAddress((void**)&VTl, g_VTl);
    cudaGetSymbolAddress((void**)&Sc, g_S);
    cudaGetSymbolAddress((void**)&Att, g_Att);
    cudaGetSymbolAddress((void**)&cnt, g_cnt);
    cudaGetSymbolAddress((void**)&c2o, g_c2o);   cudaGetSymbolAddress((void**)&o2s, g_o2s);
    cudaGetSymbolAddress((void**)&mv, g_mv);

    cudaFuncSetAttribute(mma_gemm_kernel<0>, cudaFuncAttributeMaxDynamicSharedMemorySize, GEMM_SMEM);
    cudaFuncSetAttribute(mma_gemm_kernel<1>, cudaFuncAttributeMaxDynamicSharedMemorySize, GEMM_SMEM);
    cudaFuncSetAttribute(mma_gemm_kernel<2>, cudaFuncAttributeMaxDynamicSharedMemorySize, GEMM_SMEM);
    cudaFuncSetAttribute(mma_gemm_kernel<3>, cudaFuncAttributeMaxDynamicSharedMemorySize, GEMM_SMEM);
    cudaFuncSetAttribute(pv_kernel,          cudaFuncAttributeMaxDynamicSharedMemorySize, PV_SMEM);

    // Streams/events created ONCE on the first call (before the harness's
    // pre-capture memory baseline); reused by capture/replays.
    static cudaStream_t s1 = nullptr, s2 = nullptr;
    static cudaEvent_t eInit = nullptr, eK = nullptr, eQ = nullptr,
                       eVT = nullptr, eS2 = nullptr, eS1end = nullptr;
    if (s1 == nullptr) {
        cudaStreamCreateWithFlags(&s1, cudaStreamNonBlocking);
        cudaStreamCreateWithFlags(&s2, cudaStreamNonBlocking);
        cudaEventCreateWithFlags(&eInit,  cudaEventDisableTiming);
        cudaEventCreateWithFlags(&eK,     cudaEventDisableTiming);
        cudaEventCreateWithFlags(&eQ,     cudaEventDisableTiming);
        cudaEventCreateWithFlags(&eVT,    cudaEventDisableTiming);
        cudaEventCreateWithFlags(&eS2,    cudaEventDisableTiming);
        cudaEventCreateWithFlags(&eS1end, cudaEventDisableTiming);
    }

    dim3 blk(256);
    const int HB = B_ / 2;                       // 4 batches per chain
    const long long sHalf = (long long)HB * S_ * S_;

    // ---- s0 (origin): prep ----
    compact_kernel<<<B_, blk>>>(mask, cnt, c2o, o2s);
    split_kernel<<<(MTOT * D_ / 4 + 255) / 256, blk>>>(x, xh, xl, MTOT * D_);
    {
        dim3 g((D_ * D_ + 255) / 256, 3);
        transpose_split3_kernel<<<g, blk>>>(Wq, Wk, Wv, WqTh, WqTl, WkTh, WkTl, WvTh, WvTl);
    }
    cudaEventRecord(eInit, 0);
    cudaStreamWaitEvent(s1, eInit, 0);
    cudaStreamWaitEvent(s2, eInit, 0);

    // ---- s0: Q proj (compacted gather) ----
    {
        dim3 grid(D_ / 128, S_ / 128, B_);
        mma_gemm_kernel<3><<<grid, blk, GEMM_SMEM>>>(
            xh, xl, D_, 0, WqTh, WqTl, D_, 0,
            nullptr, Qh, Ql, D_, (long long)S_ * D_, bq, D_, cnt, c2o);
        cudaEventRecord(eQ, 0);
    }
    // ---- s1: K proj (concurrent) ----
    {
        dim3 grid(D_ / 128, MTOT / 128, 1);
        mma_gemm_kernel<1><<<grid, blk, GEMM_SMEM, s1>>>(
            xh, xl, D_, 0, WkTh, WkTl, D_, 0,
            nullptr, Kh, Kl, D_, 0, bk, D_, nullptr, nullptr);
        cudaEventRecord(eK, s1);
    }
    // ---- s2: V^T proj + vmean + masked fill ----
    {
        dim3 grid(MTOT / 128, D_ / 128, 1);
        mma_gemm_kernel<2><<<grid, blk, GEMM_SMEM, s2>>>(
            WvTh, WvTl, D_, 0, xh, xl, D_, 0,
            nullptr, (__nv_bfloat16*)VTh, (__nv_bfloat16*)VTl, MTOT, 0, bv, D_,
            nullptr, nullptr);
        cudaEventRecord(eVT, s2);
        dim3 g(D_, B_);
        vmean_kernel<<<g, blk, 0, s2>>>(VTh, VTl, mv);
        fill_masked_kernel<<<MTOT, blk, 0, s2>>>(mask, mv, out);
        cudaEventRecord(eS2, s2);
    }

    // ---- chain A on s0 (batches 0..3) ----
    cudaStreamWaitEvent(0, eK, 0);               // s0 has Qproj natively
    {
        dim3 grid(S_ / 128, S_ / 128, HB);
        mma_gemm_kernel<0><<<grid, blk, GEMM_SMEM>>>(
            Qh, Ql, D_, (long long)S_ * D_,
            Kh, Kl, D_, (long long)S_ * D_,
            Sc, nullptr, nullptr, S_, (long long)S_ * S_, nullptr, D_, cnt, nullptr);
    }
    softmax_kernel<<<HB * S_, blk>>>(cnt, Sc, Att);
    cudaStreamWaitEvent(0, eVT, 0);              // latest possible point: only pv blocked
    {
        dim3 grid(D_ / 128, S_ / 128, HB);
        pv_kernel<<<grid, blk, PV_SMEM>>>(Att, VTh, VTl, out, cnt, c2o);
    }

    // ---- chain B on s1 (batches 4..7) ----
    cudaStreamWaitEvent(s1, eQ, 0);              // s1 has Kproj natively
    {
        dim3 grid(S_ / 128, S_ / 128, HB);
        mma_gemm_kernel<0><<<grid, blk, GEMM_SMEM, s1>>>(
            Qh + (long long)HB * S_ * D_, Ql + (long long)HB * S_ * D_, D_, (long long)S_ * D_,
            Kh + (long long)HB * S_ * D_, Kl + (long long)HB * S_ * D_, D_, (long long)S_ * D_,
            Sc + sHalf, nullptr, nullptr, S_, (long long)S_ * S_, nullptr, D_, cnt + HB, nullptr);
    }
    softmax_kernel<<<HB * S_, blk, 0, s1>>>(cnt + HB, Sc + sHalf, Att + sHalf);
    cudaStreamWaitEvent(s1, eVT, 0);             // latest possible point
    {
        dim3 grid(D_ / 128, S_ / 128, HB);
        pv_kernel<<<grid, blk, PV_SMEM, s1>>>(
            Att + sHalf, VTh + (long long)HB * S_, VTl + (long long)HB * S_,
            out, cnt + HB, c2o + (long long)HB * S_);
    }
    cudaEventRecord(eS1end, s1);

    // ---- join s1 and s2 back into origin ----
    cudaStreamWaitEvent(0, eS1end, 0);
    cudaStreamWaitEvent(0, eS2, 0);
}